// round 1
// baseline (speedup 1.0000x reference)
#include <cuda_runtime.h>
#include <cuda_bf16.h>

#define FDIM 128
#define MAXN 100000
#define TM 64
#define KC 16

// Scratch: LE accumulator + transposed weights (k-major)
__device__ float g_LE[MAXN * FDIM];
__device__ float g_Wt1[FDIM * FDIM];
__device__ float g_Wt2[FDIM * FDIM];

// ---------------------------------------------------------------------------
// Zero LE
// ---------------------------------------------------------------------------
__global__ void zero_le_kernel(int total4) {
    int i = blockIdx.x * blockDim.x + threadIdx.x;
    if (i < total4) {
        reinterpret_cast<float4*>(g_LE)[i] = make_float4(0.f, 0.f, 0.f, 0.f);
    }
}

// ---------------------------------------------------------------------------
// Transpose W1,W2 into k-major: Wt[k][j] = W[j][k]
// ---------------------------------------------------------------------------
__global__ void transpose_w_kernel(const float* __restrict__ W1,
                                   const float* __restrict__ W2) {
    int i = blockIdx.x * blockDim.x + threadIdx.x;  // 0 .. 128*128-1
    if (i < FDIM * FDIM) {
        int c = i & (FDIM - 1);   // j (output col), fast index -> coalesced store
        int k = i >> 7;           // k
        g_Wt1[k * FDIM + c] = W1[c * FDIM + k];
        g_Wt2[k * FDIM + c] = W2[c * FDIM + k];
    }
}

// ---------------------------------------------------------------------------
// Edge scatter: LE[dst] += val * feats[src]
// One warp per edge; lane c handles float4 chunk c (32 chunks x 4 = 128).
// ---------------------------------------------------------------------------
__global__ void __launch_bounds__(256)
scatter_kernel(const int* __restrict__ src, const int* __restrict__ dst,
               const float* __restrict__ val, const float* __restrict__ feats,
               int E) {
    long long tid = (long long)blockIdx.x * blockDim.x + threadIdx.x;
    int e = (int)(tid >> 5);
    int c = (int)(tid & 31);
    if (e >= E) return;
    int s = src[e];
    int d = dst[e];
    float v = val[e];
    float4 f = *reinterpret_cast<const float4*>(&feats[(long long)s * FDIM + c * 4]);
    float* o = &g_LE[(long long)d * FDIM + c * 4];
    atomicAdd(o + 0, v * f.x);
    atomicAdd(o + 1, v * f.y);
    atomicAdd(o + 2, v * f.z);
    atomicAdd(o + 3, v * f.w);
}

// ---------------------------------------------------------------------------
// Fused dense: out = (LE+feats)@W1^T + (LE*feats)@W2^T + (b1+b2)
// Block: 256 threads, tile = 64 rows x 128 cols.
// tx (0..31) -> 4 consecutive output cols (tx*4..tx*4+3)
// ty (0..7)  -> 8 consecutive rows (ty*8..ty*8+7)
// ---------------------------------------------------------------------------
__global__ void __launch_bounds__(256)
gemm_kernel(const float* __restrict__ feats,
            const float* __restrict__ b1, const float* __restrict__ b2,
            float* __restrict__ out, int N) {
    __shared__ float w1s[KC][FDIM];
    __shared__ float w2s[KC][FDIM];
    __shared__ float as[TM][KC];
    __shared__ float es[TM][KC];

    int tid = threadIdx.x;
    int tx = tid & 31;
    int ty = tid >> 5;
    int row0 = blockIdx.x * TM;

    float4 acc[8];
#pragma unroll
    for (int r = 0; r < 8; ++r) acc[r] = make_float4(0.f, 0.f, 0.f, 0.f);

    for (int kc = 0; kc < FDIM; kc += KC) {
        // Load transposed weight chunks: coalesced global, conflict-free STS.
#pragma unroll
        for (int i = tid; i < KC * FDIM; i += 256) {
            int c = i & (FDIM - 1);
            int k = i >> 7;
            w1s[k][c] = g_Wt1[(kc + k) * FDIM + c];
            w2s[k][c] = g_Wt2[(kc + k) * FDIM + c];
        }
        // Load a = LE+feats, e = LE*feats for this row tile / k chunk.
#pragma unroll
        for (int i = tid; i < TM * KC; i += 256) {
            int k = i & (KC - 1);
            int r = i >> 4;
            int row = row0 + r;
            float le = 0.f, ft = 0.f;
            if (row < N) {
                le = g_LE[(long long)row * FDIM + kc + k];
                ft = feats[(long long)row * FDIM + kc + k];
            }
            as[r][k] = le + ft;
            es[r][k] = le * ft;
        }
        __syncthreads();

#pragma unroll
        for (int k = 0; k < KC; ++k) {
            float4 w1v = reinterpret_cast<float4*>(&w1s[k][0])[tx];
            float4 w2v = reinterpret_cast<float4*>(&w2s[k][0])[tx];
#pragma unroll
            for (int r = 0; r < 8; ++r) {
                float av = as[ty * 8 + r][k];
                float ev = es[ty * 8 + r][k];
                acc[r].x += av * w1v.x;
                acc[r].x += ev * w2v.x;
                acc[r].y += av * w1v.y;
                acc[r].y += ev * w2v.y;
                acc[r].z += av * w1v.z;
                acc[r].z += ev * w2v.z;
                acc[r].w += av * w1v.w;
                acc[r].w += ev * w2v.w;
            }
        }
        __syncthreads();
    }

    // Bias and store.
    int c0 = tx * 4;
    float4 bv;
    bv.x = b1[c0 + 0] + b2[c0 + 0];
    bv.y = b1[c0 + 1] + b2[c0 + 1];
    bv.z = b1[c0 + 2] + b2[c0 + 2];
    bv.w = b1[c0 + 3] + b2[c0 + 3];
#pragma unroll
    for (int r = 0; r < 8; ++r) {
        int row = row0 + ty * 8 + r;
        if (row < N) {
            float4 o;
            o.x = acc[r].x + bv.x;
            o.y = acc[r].y + bv.y;
            o.z = acc[r].z + bv.z;
            o.w = acc[r].w + bv.w;
            *reinterpret_cast<float4*>(&out[(long long)row * FDIM + c0]) = o;
        }
    }
}

// ---------------------------------------------------------------------------
extern "C" void kernel_launch(void* const* d_in, const int* in_sizes, int n_in,
                              void* d_out, int out_size) {
    const int*   src   = (const int*)d_in[0];
    const int*   dst   = (const int*)d_in[1];
    const float* val   = (const float*)d_in[2];
    const float* feats = (const float*)d_in[3];
    const float* W1    = (const float*)d_in[4];
    const float* b1    = (const float*)d_in[5];
    const float* W2    = (const float*)d_in[6];
    const float* b2    = (const float*)d_in[7];
    float* out = (float*)d_out;

    int E = in_sizes[0];
    int N = in_sizes[3] / FDIM;

    int total4 = N * FDIM / 4;
    zero_le_kernel<<<(total4 + 255) / 256, 256>>>(total4);
    transpose_w_kernel<<<(FDIM * FDIM + 255) / 256, 256>>>(W1, W2);

    long long scatter_threads = (long long)E * 32;
    int scatter_blocks = (int)((scatter_threads + 255) / 256);
    scatter_kernel<<<scatter_blocks, 256>>>(src, dst, val, feats, E);

    gemm_kernel<<<(N + TM - 1) / TM, 256>>>(feats, b1, b2, out, N);
}

// round 2
// speedup vs baseline: 2.1721x; 2.1721x over previous
#include <cuda_runtime.h>
#include <cuda_bf16.h>

#define FDIM 128
#define MAXN 100000
#define MAXE 1600000
#define TM 64
#define KC 16
#define SEG 1024          // elements per scan segment
#define MAXSEG 128        // ceil(MAXN/SEG) <= 128

// Scratch
__device__ float g_LE[MAXN * FDIM];
__device__ float g_Wt1[FDIM * FDIM];
__device__ float g_Wt2[FDIM * FDIM];
__device__ int   g_cnt[MAXN];
__device__ int   g_off[MAXN + 1];
__device__ int   g_cur[MAXN];
__device__ int   g_bsum[MAXSEG];
__device__ int   g_esrc[MAXE];
__device__ float g_eval[MAXE];

// ---------------------------------------------------------------------------
// Zero counts
// ---------------------------------------------------------------------------
__global__ void zero_cnt_kernel(int N) {
    int i = blockIdx.x * blockDim.x + threadIdx.x;
    if (i < N) g_cnt[i] = 0;
}

// ---------------------------------------------------------------------------
// Transpose W1,W2 into k-major: Wt[k][j] = W[j][k]
// ---------------------------------------------------------------------------
__global__ void transpose_w_kernel(const float* __restrict__ W1,
                                   const float* __restrict__ W2) {
    int i = blockIdx.x * blockDim.x + threadIdx.x;
    if (i < FDIM * FDIM) {
        int c = i & (FDIM - 1);
        int k = i >> 7;
        g_Wt1[k * FDIM + c] = W1[c * FDIM + k];
        g_Wt2[k * FDIM + c] = W2[c * FDIM + k];
    }
}

// ---------------------------------------------------------------------------
// Histogram of dst
// ---------------------------------------------------------------------------
__global__ void hist_kernel(const int* __restrict__ dst, int E) {
    int e = blockIdx.x * blockDim.x + threadIdx.x;
    if (e < E) atomicAdd(&g_cnt[dst[e]], 1);
}

// ---------------------------------------------------------------------------
// Scan stage 1: per-segment sums (SEG=1024, 256 threads x 4 elems)
// ---------------------------------------------------------------------------
__global__ void __launch_bounds__(256) scan1_kernel(int N) {
    __shared__ int ssum[256];
    int t = threadIdx.x;
    int base = blockIdx.x * SEG + t * 4;
    int s = 0;
#pragma unroll
    for (int j = 0; j < 4; ++j) {
        int idx = base + j;
        if (idx < N) s += g_cnt[idx];
    }
    ssum[t] = s;
    __syncthreads();
#pragma unroll
    for (int off = 128; off > 0; off >>= 1) {
        if (t < off) ssum[t] += ssum[t + off];
        __syncthreads();
    }
    if (t == 0) g_bsum[blockIdx.x] = ssum[0];
}

// ---------------------------------------------------------------------------
// Scan stage 2: exclusive scan of segment sums (nseg <= 128), single block
// ---------------------------------------------------------------------------
__global__ void scan2_kernel(int nseg, int N, int E) {
    __shared__ int sv[MAXSEG];
    int t = threadIdx.x;  // 128 threads
    int v = (t < nseg) ? g_bsum[t] : 0;
    sv[t] = v;
    __syncthreads();
#pragma unroll
    for (int off = 1; off < MAXSEG; off <<= 1) {
        int x = (t >= off) ? sv[t - off] : 0;
        __syncthreads();
        sv[t] += x;
        __syncthreads();
    }
    if (t < nseg) g_bsum[t] = sv[t] - v;  // exclusive
    if (t == 0) g_off[N] = E;
}

// ---------------------------------------------------------------------------
// Scan stage 3: per-segment exclusive scan + segment offset -> g_off, g_cur
// ---------------------------------------------------------------------------
__global__ void __launch_bounds__(256) scan3_kernel(int N) {
    __shared__ int ssum[256];
    int t = threadIdx.x;
    int base = blockIdx.x * SEG + t * 4;
    int c[4];
    int tsum = 0;
#pragma unroll
    for (int j = 0; j < 4; ++j) {
        int idx = base + j;
        c[j] = (idx < N) ? g_cnt[idx] : 0;
        tsum += c[j];
    }
    ssum[t] = tsum;
    __syncthreads();
#pragma unroll
    for (int off = 1; off < 256; off <<= 1) {
        int x = (t >= off) ? ssum[t - off] : 0;
        __syncthreads();
        ssum[t] += x;
        __syncthreads();
    }
    int excl = ssum[t] - tsum;
    int pos = g_bsum[blockIdx.x] + excl;
#pragma unroll
    for (int j = 0; j < 4; ++j) {
        int idx = base + j;
        if (idx < N) {
            g_off[idx] = pos;
            g_cur[idx] = pos;
            pos += c[j];
        }
    }
}

// ---------------------------------------------------------------------------
// Permute edges into CSR order
// ---------------------------------------------------------------------------
__global__ void permute_kernel(const int* __restrict__ src,
                               const int* __restrict__ dst,
                               const float* __restrict__ val, int E) {
    int e = blockIdx.x * blockDim.x + threadIdx.x;
    if (e < E) {
        int d = dst[e];
        int p = atomicAdd(&g_cur[d], 1);
        g_esrc[p] = src[e];
        g_eval[p] = val[e];
    }
}

// ---------------------------------------------------------------------------
// Gather: one warp per node.  LE[n] = sum_e val[e] * feats[src[e]]
// Lane c owns float4 chunk c of the 128-wide row.
// ---------------------------------------------------------------------------
__global__ void __launch_bounds__(256)
gather_kernel(const float* __restrict__ feats, int N) {
    int warp = (blockIdx.x << 3) + (threadIdx.x >> 5);
    if (warp >= N) return;
    int lane = threadIdx.x & 31;
    int start = g_off[warp];
    int end = g_off[warp + 1];

    float4 acc = make_float4(0.f, 0.f, 0.f, 0.f);
    for (int base = start; base < end; base += 32) {
        int n = end - base;
        if (n > 32) n = 32;
        int s = 0;
        float v = 0.f;
        if (lane < n) {
            s = g_esrc[base + lane];
            v = g_eval[base + lane];
        }
#pragma unroll 4
        for (int j = 0; j < n; ++j) {
            int sj = __shfl_sync(0xffffffff, s, j);
            float vj = __shfl_sync(0xffffffff, v, j);
            float4 f = *reinterpret_cast<const float4*>(
                &feats[(long long)sj * FDIM + lane * 4]);
            acc.x += vj * f.x;
            acc.y += vj * f.y;
            acc.z += vj * f.z;
            acc.w += vj * f.w;
        }
    }
    *reinterpret_cast<float4*>(&g_LE[(long long)warp * FDIM + lane * 4]) = acc;
}

// ---------------------------------------------------------------------------
// Fused dense: out = (LE+feats)@W1^T + (LE*feats)@W2^T + (b1+b2)
// ---------------------------------------------------------------------------
__global__ void __launch_bounds__(256)
gemm_kernel(const float* __restrict__ feats,
            const float* __restrict__ b1, const float* __restrict__ b2,
            float* __restrict__ out, int N) {
    __shared__ float w1s[KC][FDIM];
    __shared__ float w2s[KC][FDIM];
    __shared__ float as[TM][KC];
    __shared__ float es[TM][KC];

    int tid = threadIdx.x;
    int tx = tid & 31;
    int ty = tid >> 5;
    int row0 = blockIdx.x * TM;

    float4 acc[8];
#pragma unroll
    for (int r = 0; r < 8; ++r) acc[r] = make_float4(0.f, 0.f, 0.f, 0.f);

    for (int kc = 0; kc < FDIM; kc += KC) {
#pragma unroll
        for (int i = tid; i < KC * FDIM; i += 256) {
            int c = i & (FDIM - 1);
            int k = i >> 7;
            w1s[k][c] = g_Wt1[(kc + k) * FDIM + c];
            w2s[k][c] = g_Wt2[(kc + k) * FDIM + c];
        }
#pragma unroll
        for (int i = tid; i < TM * KC; i += 256) {
            int k = i & (KC - 1);
            int r = i >> 4;
            int row = row0 + r;
            float le = 0.f, ft = 0.f;
            if (row < N) {
                le = g_LE[(long long)row * FDIM + kc + k];
                ft = feats[(long long)row * FDIM + kc + k];
            }
            as[r][k] = le + ft;
            es[r][k] = le * ft;
        }
        __syncthreads();

#pragma unroll
        for (int k = 0; k < KC; ++k) {
            float4 w1v = reinterpret_cast<float4*>(&w1s[k][0])[tx];
            float4 w2v = reinterpret_cast<float4*>(&w2s[k][0])[tx];
#pragma unroll
            for (int r = 0; r < 8; ++r) {
                float av = as[ty * 8 + r][k];
                float ev = es[ty * 8 + r][k];
                acc[r].x += av * w1v.x;
                acc[r].x += ev * w2v.x;
                acc[r].y += av * w1v.y;
                acc[r].y += ev * w2v.y;
                acc[r].z += av * w1v.z;
                acc[r].z += ev * w2v.z;
                acc[r].w += av * w1v.w;
                acc[r].w += ev * w2v.w;
            }
        }
        __syncthreads();
    }

    int c0 = tx * 4;
    float4 bv;
    bv.x = b1[c0 + 0] + b2[c0 + 0];
    bv.y = b1[c0 + 1] + b2[c0 + 1];
    bv.z = b1[c0 + 2] + b2[c0 + 2];
    bv.w = b1[c0 + 3] + b2[c0 + 3];
#pragma unroll
    for (int r = 0; r < 8; ++r) {
        int row = row0 + ty * 8 + r;
        if (row < N) {
            float4 o;
            o.x = acc[r].x + bv.x;
            o.y = acc[r].y + bv.y;
            o.z = acc[r].z + bv.z;
            o.w = acc[r].w + bv.w;
            *reinterpret_cast<float4*>(&out[(long long)row * FDIM + c0]) = o;
        }
    }
}

// ---------------------------------------------------------------------------
extern "C" void kernel_launch(void* const* d_in, const int* in_sizes, int n_in,
                              void* d_out, int out_size) {
    const int*   src   = (const int*)d_in[0];
    const int*   dst   = (const int*)d_in[1];
    const float* val   = (const float*)d_in[2];
    const float* feats = (const float*)d_in[3];
    const float* W1    = (const float*)d_in[4];
    const float* b1    = (const float*)d_in[5];
    const float* W2    = (const float*)d_in[6];
    const float* b2    = (const float*)d_in[7];
    float* out = (float*)d_out;

    int E = in_sizes[0];
    int N = in_sizes[3] / FDIM;
    int nseg = (N + SEG - 1) / SEG;

    zero_cnt_kernel<<<(N + 255) / 256, 256>>>(N);
    transpose_w_kernel<<<(FDIM * FDIM + 255) / 256, 256>>>(W1, W2);
    hist_kernel<<<(E + 255) / 256, 256>>>(dst, E);
    scan1_kernel<<<nseg, 256>>>(N);
    scan2_kernel<<<1, MAXSEG>>>(nseg, N, E);
    scan3_kernel<<<nseg, 256>>>(N);
    permute_kernel<<<(E + 255) / 256, 256>>>(src, dst, val, E);
    gather_kernel<<<(N + 7) / 8, 256>>>(feats, N);
    gemm_kernel<<<(N + TM - 1) / TM, 256>>>(feats, b1, b2, out, N);
}

// round 3
// speedup vs baseline: 2.4011x; 1.1054x over previous
#include <cuda_runtime.h>
#include <cuda_bf16.h>

#define FDIM 128
#define MAXN 100000
#define MAXE 1600000
#define TM 64
#define KC 16
#define SEG 1024          // elements per scan segment
#define MAXSEG 128        // ceil(MAXN/SEG) <= 128

// Scratch
__device__ float g_LE[MAXN * FDIM];
__device__ float g_Wt1[FDIM * FDIM];
__device__ float g_Wt2[FDIM * FDIM];
__device__ int   g_cnt[MAXN];
__device__ int   g_off[MAXN + 1];
__device__ int   g_cur[MAXN];
__device__ int   g_bsum[MAXSEG];
__device__ int   g_esrc[MAXE];
__device__ float g_eval[MAXE];

// ---------------------------------------------------------------------------
// Zero counts
// ---------------------------------------------------------------------------
__global__ void zero_cnt_kernel(int N) {
    int i = blockIdx.x * blockDim.x + threadIdx.x;
    if (i < N) g_cnt[i] = 0;
}

// ---------------------------------------------------------------------------
// Transpose W1,W2 into k-major: Wt[k][j] = W[j][k]
// ---------------------------------------------------------------------------
__global__ void transpose_w_kernel(const float* __restrict__ W1,
                                   const float* __restrict__ W2) {
    int i = blockIdx.x * blockDim.x + threadIdx.x;
    if (i < FDIM * FDIM) {
        int c = i & (FDIM - 1);
        int k = i >> 7;
        g_Wt1[k * FDIM + c] = W1[c * FDIM + k];
        g_Wt2[k * FDIM + c] = W2[c * FDIM + k];
    }
}

// ---------------------------------------------------------------------------
// Histogram of dst
// ---------------------------------------------------------------------------
__global__ void hist_kernel(const int* __restrict__ dst, int E) {
    int e = blockIdx.x * blockDim.x + threadIdx.x;
    if (e < E) atomicAdd(&g_cnt[dst[e]], 1);
}

// ---------------------------------------------------------------------------
// Scan stage 1: per-segment sums
// ---------------------------------------------------------------------------
__global__ void __launch_bounds__(256) scan1_kernel(int N) {
    __shared__ int ssum[256];
    int t = threadIdx.x;
    int base = blockIdx.x * SEG + t * 4;
    int s = 0;
#pragma unroll
    for (int j = 0; j < 4; ++j) {
        int idx = base + j;
        if (idx < N) s += g_cnt[idx];
    }
    ssum[t] = s;
    __syncthreads();
#pragma unroll
    for (int off = 128; off > 0; off >>= 1) {
        if (t < off) ssum[t] += ssum[t + off];
        __syncthreads();
    }
    if (t == 0) g_bsum[blockIdx.x] = ssum[0];
}

// ---------------------------------------------------------------------------
// Scan stage 2: exclusive scan of segment sums, single block
// ---------------------------------------------------------------------------
__global__ void scan2_kernel(int nseg, int N, int E) {
    __shared__ int sv[MAXSEG];
    int t = threadIdx.x;  // 128 threads
    int v = (t < nseg) ? g_bsum[t] : 0;
    sv[t] = v;
    __syncthreads();
#pragma unroll
    for (int off = 1; off < MAXSEG; off <<= 1) {
        int x = (t >= off) ? sv[t - off] : 0;
        __syncthreads();
        sv[t] += x;
        __syncthreads();
    }
    if (t < nseg) g_bsum[t] = sv[t] - v;  // exclusive
    if (t == 0) g_off[N] = E;
}

// ---------------------------------------------------------------------------
// Scan stage 3: per-segment exclusive scan + segment offset -> g_off, g_cur
// ---------------------------------------------------------------------------
__global__ void __launch_bounds__(256) scan3_kernel(int N) {
    __shared__ int ssum[256];
    int t = threadIdx.x;
    int base = blockIdx.x * SEG + t * 4;
    int c[4];
    int tsum = 0;
#pragma unroll
    for (int j = 0; j < 4; ++j) {
        int idx = base + j;
        c[j] = (idx < N) ? g_cnt[idx] : 0;
        tsum += c[j];
    }
    ssum[t] = tsum;
    __syncthreads();
#pragma unroll
    for (int off = 1; off < 256; off <<= 1) {
        int x = (t >= off) ? ssum[t - off] : 0;
        __syncthreads();
        ssum[t] += x;
        __syncthreads();
    }
    int excl = ssum[t] - tsum;
    int pos = g_bsum[blockIdx.x] + excl;
#pragma unroll
    for (int j = 0; j < 4; ++j) {
        int idx = base + j;
        if (idx < N) {
            g_off[idx] = pos;
            g_cur[idx] = pos;
            pos += c[j];
        }
    }
}

// ---------------------------------------------------------------------------
// Permute edges into CSR order
// ---------------------------------------------------------------------------
__global__ void permute_kernel(const int* __restrict__ src,
                               const int* __restrict__ dst,
                               const float* __restrict__ val, int E) {
    int e = blockIdx.x * blockDim.x + threadIdx.x;
    if (e < E) {
        int d = dst[e];
        int p = atomicAdd(&g_cur[d], 1);
        g_esrc[p] = src[e];
        g_eval[p] = val[e];
    }
}

// ---------------------------------------------------------------------------
// Gather: one warp per node.  LE[n] = sum_e val[e] * feats[src[e]]
// ---------------------------------------------------------------------------
__global__ void __launch_bounds__(256)
gather_kernel(const float* __restrict__ feats, int N) {
    int warp = (blockIdx.x << 3) + (threadIdx.x >> 5);
    if (warp >= N) return;
    int lane = threadIdx.x & 31;
    int start = g_off[warp];
    int end = g_off[warp + 1];

    float4 acc = make_float4(0.f, 0.f, 0.f, 0.f);
    for (int base = start; base < end; base += 32) {
        int n = end - base;
        if (n > 32) n = 32;
        int s = 0;
        float v = 0.f;
        if (lane < n) {
            s = g_esrc[base + lane];
            v = g_eval[base + lane];
        }
#pragma unroll 4
        for (int j = 0; j < n; ++j) {
            int sj = __shfl_sync(0xffffffff, s, j);
            float vj = __shfl_sync(0xffffffff, v, j);
            float4 f = *reinterpret_cast<const float4*>(
                &feats[(long long)sj * FDIM + lane * 4]);
            acc.x += vj * f.x;
            acc.y += vj * f.y;
            acc.z += vj * f.z;
            acc.w += vj * f.w;
        }
    }
    *reinterpret_cast<float4*>(&g_LE[(long long)warp * FDIM + lane * 4]) = acc;
}

// ---------------------------------------------------------------------------
// FFMA2 helpers
// ---------------------------------------------------------------------------
__device__ __forceinline__ void fma2(unsigned long long& d,
                                     unsigned long long a,
                                     unsigned long long b) {
    asm("fma.rn.f32x2 %0, %1, %2, %0;" : "+l"(d) : "l"(a), "l"(b));
}
__device__ __forceinline__ unsigned long long dup2(float w) {
    unsigned long long d;
    asm("mov.b64 %0, {%1, %1};" : "=l"(d) : "f"(w));
    return d;
}
__device__ __forceinline__ void unpack2(unsigned long long v, float& lo, float& hi) {
    asm("mov.b64 {%0, %1}, %2;" : "=f"(lo), "=f"(hi) : "l"(v));
}

// ---------------------------------------------------------------------------
// Fused dense: out = (LE+feats)@W1^T + (LE*feats)@W2^T + (b1+b2)
// Packed f32x2: each 64-bit accumulator holds two adjacent rows for one col.
// Block: 256 threads, tile = 64 rows x 128 cols.
// tx (0..31) -> 4 consecutive output cols (tx*4..tx*4+3)
// ty (0..7)  -> 4 row-pairs = rows ty*8 .. ty*8+7
// ---------------------------------------------------------------------------
#define TMP (TM + 2)   // padded row length for transposed a/e tiles (8B-aligned)

__global__ void __launch_bounds__(256)
gemm_kernel(const float* __restrict__ feats,
            const float* __restrict__ b1, const float* __restrict__ b2,
            float* __restrict__ out, int N) {
    __shared__ __align__(16) float w1s[KC][FDIM];
    __shared__ __align__(16) float w2s[KC][FDIM];
    __shared__ __align__(16) float as[KC][TMP];   // transposed: as[k][row]
    __shared__ __align__(16) float es[KC][TMP];

    int tid = threadIdx.x;
    int tx = tid & 31;
    int ty = tid >> 5;
    int row0 = blockIdx.x * TM;

    unsigned long long acc[4][4];   // [row-pair][col] each = 2 rows packed
#pragma unroll
    for (int rp = 0; rp < 4; ++rp)
#pragma unroll
        for (int c = 0; c < 4; ++c) acc[rp][c] = 0ull;

    for (int kc = 0; kc < FDIM; kc += KC) {
        // Weights: coalesced global, conflict-free STS.
#pragma unroll
        for (int i = tid; i < KC * FDIM; i += 256) {
            int c = i & (FDIM - 1);
            int k = i >> 7;
            w1s[k][c] = g_Wt1[(kc + k) * FDIM + c];
            w2s[k][c] = g_Wt2[(kc + k) * FDIM + c];
        }
        // a = LE+feats, e = LE*feats -> transposed smem [k][row].
        // k fast in i for coalesced global; store banks k*TMP+r = 66k+r -> distinct.
#pragma unroll
        for (int i = tid; i < TM * KC; i += 256) {
            int k = i & (KC - 1);
            int r = i >> 4;
            int row = row0 + r;
            float le = 0.f, ft = 0.f;
            if (row < N) {
                le = g_LE[(long long)row * FDIM + kc + k];
                ft = feats[(long long)row * FDIM + kc + k];
            }
            as[k][r] = le + ft;
            es[k][r] = le * ft;
        }
        __syncthreads();

#pragma unroll
        for (int k = 0; k < KC; ++k) {
            float4 w1v = *reinterpret_cast<float4*>(&w1s[k][tx * 4]);
            float4 w2v = *reinterpret_cast<float4*>(&w2s[k][tx * 4]);
            unsigned long long W1d[4], W2d[4];
            W1d[0] = dup2(w1v.x); W1d[1] = dup2(w1v.y);
            W1d[2] = dup2(w1v.z); W1d[3] = dup2(w1v.w);
            W2d[0] = dup2(w2v.x); W2d[1] = dup2(w2v.y);
            W2d[2] = dup2(w2v.z); W2d[3] = dup2(w2v.w);
#pragma unroll
            for (int rp = 0; rp < 4; ++rp) {
                // rows ty*8 + 2*rp, ty*8 + 2*rp + 1  (broadcast LDS.64)
                unsigned long long a2 = *reinterpret_cast<unsigned long long*>(
                    &as[k][ty * 8 + rp * 2]);
                unsigned long long e2 = *reinterpret_cast<unsigned long long*>(
                    &es[k][ty * 8 + rp * 2]);
#pragma unroll
                for (int c = 0; c < 4; ++c) {
                    fma2(acc[rp][c], a2, W1d[c]);
                    fma2(acc[rp][c], e2, W2d[c]);
                }
            }
        }
        __syncthreads();
    }

    // Bias + store (unpack row pairs).
    int c0 = tx * 4;
    float bv[4];
#pragma unroll
    for (int c = 0; c < 4; ++c) bv[c] = b1[c0 + c] + b2[c0 + c];

#pragma unroll
    for (int rp = 0; rp < 4; ++rp) {
        float lo[4], hi[4];
#pragma unroll
        for (int c = 0; c < 4; ++c) unpack2(acc[rp][c], lo[c], hi[c]);
        int r_even = row0 + ty * 8 + rp * 2;
        if (r_even < N) {
            float4 o;
            o.x = lo[0] + bv[0]; o.y = lo[1] + bv[1];
            o.z = lo[2] + bv[2]; o.w = lo[3] + bv[3];
            *reinterpret_cast<float4*>(&out[(long long)r_even * FDIM + c0]) = o;
        }
        if (r_even + 1 < N) {
            float4 o;
            o.x = hi[0] + bv[0]; o.y = hi[1] + bv[1];
            o.z = hi[2] + bv[2]; o.w = hi[3] + bv[3];
            *reinterpret_cast<float4*>(&out[(long long)(r_even + 1) * FDIM + c0]) = o;
        }
    }
}

// ---------------------------------------------------------------------------
extern "C" void kernel_launch(void* const* d_in, const int* in_sizes, int n_in,
                              void* d_out, int out_size) {
    const int*   src   = (const int*)d_in[0];
    const int*   dst   = (const int*)d_in[1];
    const float* val   = (const float*)d_in[2];
    const float* feats = (const float*)d_in[3];
    const float* W1    = (const float*)d_in[4];
    const float* b1    = (const float*)d_in[5];
    const float* W2    = (const float*)d_in[6];
    const float* b2    = (const float*)d_in[7];
    float* out = (float*)d_out;

    int E = in_sizes[0];
    int N = in_sizes[3] / FDIM;
    int nseg = (N + SEG - 1) / SEG;

    zero_cnt_kernel<<<(N + 255) / 256, 256>>>(N);
    transpose_w_kernel<<<(FDIM * FDIM + 255) / 256, 256>>>(W1, W2);
    hist_kernel<<<(E + 255) / 256, 256>>>(dst, E);
    scan1_kernel<<<nseg, 256>>>(N);
    scan2_kernel<<<1, MAXSEG>>>(nseg, N, E);
    scan3_kernel<<<nseg, 256>>>(N);
    permute_kernel<<<(E + 255) / 256, 256>>>(src, dst, val, E);
    gather_kernel<<<(N + 7) / 8, 256>>>(feats, N);
    gemm_kernel<<<(N + TM - 1) / TM, 256>>>(feats, b1, b2, out, N);
}

// round 5
// speedup vs baseline: 3.1411x; 1.3082x over previous
#include <cuda_runtime.h>
#include <cuda_bf16.h>
#include <cstdint>

#define FDIM 128
#define MAXN 100000
#define MAXE 1600000
#define SEG 1024
#define MAXSEG 128

// ---------------------------------------------------------------------------
// Scratch
// ---------------------------------------------------------------------------
__device__ float g_LE[MAXN * FDIM];
__device__ int   g_cnt[MAXN];
__device__ int   g_off[MAXN + 1];
__device__ int   g_cur[MAXN];
__device__ int   g_bsum[MAXSEG];
__device__ int   g_esrc[MAXE];
__device__ float g_eval[MAXE];

// ---------------------------------------------------------------------------
// Zero counts
// ---------------------------------------------------------------------------
__global__ void zero_cnt_kernel(int N) {
    int i = blockIdx.x * blockDim.x + threadIdx.x;
    if (i < N) g_cnt[i] = 0;
}

// ---------------------------------------------------------------------------
// Histogram of dst
// ---------------------------------------------------------------------------
__global__ void hist_kernel(const int* __restrict__ dst, int E) {
    int e = blockIdx.x * blockDim.x + threadIdx.x;
    if (e < E) atomicAdd(&g_cnt[dst[e]], 1);
}

// ---------------------------------------------------------------------------
// Scan stage 1
// ---------------------------------------------------------------------------
__global__ void __launch_bounds__(256) scan1_kernel(int N) {
    __shared__ int ssum[256];
    int t = threadIdx.x;
    int base = blockIdx.x * SEG + t * 4;
    int s = 0;
#pragma unroll
    for (int j = 0; j < 4; ++j) {
        int idx = base + j;
        if (idx < N) s += g_cnt[idx];
    }
    ssum[t] = s;
    __syncthreads();
#pragma unroll
    for (int off = 128; off > 0; off >>= 1) {
        if (t < off) ssum[t] += ssum[t + off];
        __syncthreads();
    }
    if (t == 0) g_bsum[blockIdx.x] = ssum[0];
}

// ---------------------------------------------------------------------------
// Scan stage 2
// ---------------------------------------------------------------------------
__global__ void scan2_kernel(int nseg, int N, int E) {
    __shared__ int sv[MAXSEG];
    int t = threadIdx.x;
    int v = (t < nseg) ? g_bsum[t] : 0;
    sv[t] = v;
    __syncthreads();
#pragma unroll
    for (int off = 1; off < MAXSEG; off <<= 1) {
        int x = (t >= off) ? sv[t - off] : 0;
        __syncthreads();
        sv[t] += x;
        __syncthreads();
    }
    if (t < nseg) g_bsum[t] = sv[t] - v;
    if (t == 0) g_off[N] = E;
}

// ---------------------------------------------------------------------------
// Scan stage 3
// ---------------------------------------------------------------------------
__global__ void __launch_bounds__(256) scan3_kernel(int N) {
    __shared__ int ssum[256];
    int t = threadIdx.x;
    int base = blockIdx.x * SEG + t * 4;
    int c[4];
    int tsum = 0;
#pragma unroll
    for (int j = 0; j < 4; ++j) {
        int idx = base + j;
        c[j] = (idx < N) ? g_cnt[idx] : 0;
        tsum += c[j];
    }
    ssum[t] = tsum;
    __syncthreads();
#pragma unroll
    for (int off = 1; off < 256; off <<= 1) {
        int x = (t >= off) ? ssum[t - off] : 0;
        __syncthreads();
        ssum[t] += x;
        __syncthreads();
    }
    int excl = ssum[t] - tsum;
    int pos = g_bsum[blockIdx.x] + excl;
#pragma unroll
    for (int j = 0; j < 4; ++j) {
        int idx = base + j;
        if (idx < N) {
            g_off[idx] = pos;
            g_cur[idx] = pos;
            pos += c[j];
        }
    }
}

// ---------------------------------------------------------------------------
// Permute edges into CSR order
// ---------------------------------------------------------------------------
__global__ void permute_kernel(const int* __restrict__ src,
                               const int* __restrict__ dst,
                               const float* __restrict__ val, int E) {
    int e = blockIdx.x * blockDim.x + threadIdx.x;
    if (e < E) {
        int d = dst[e];
        int p = atomicAdd(&g_cur[d], 1);
        g_esrc[p] = src[e];
        g_eval[p] = val[e];
    }
}

// ---------------------------------------------------------------------------
// Gather: one warp per node.  LE[n] = sum_e val[e] * feats[src[e]]
// ---------------------------------------------------------------------------
__global__ void __launch_bounds__(256)
gather_kernel(const float* __restrict__ feats, int N) {
    int warp = (blockIdx.x << 3) + (threadIdx.x >> 5);
    if (warp >= N) return;
    int lane = threadIdx.x & 31;
    int start = g_off[warp];
    int end = g_off[warp + 1];

    float4 acc = make_float4(0.f, 0.f, 0.f, 0.f);
    for (int base = start; base < end; base += 32) {
        int n = end - base;
        if (n > 32) n = 32;
        int s = 0;
        float v = 0.f;
        if (lane < n) {
            s = g_esrc[base + lane];
            v = g_eval[base + lane];
        }
#pragma unroll 4
        for (int j = 0; j < n; ++j) {
            int sj = __shfl_sync(0xffffffff, s, j);
            float vj = __shfl_sync(0xffffffff, v, j);
            float4 f = *reinterpret_cast<const float4*>(
                &feats[(long long)sj * FDIM + lane * 4]);
            acc.x += vj * f.x;
            acc.y += vj * f.y;
            acc.z += vj * f.z;
            acc.w += vj * f.w;
        }
    }
    *reinterpret_cast<float4*>(&g_LE[(long long)warp * FDIM + lane * 4]) = acc;
}

// ---------------------------------------------------------------------------
// HMMA helpers
// ---------------------------------------------------------------------------
// pack two fp32 -> bf16x2: lower half = lo, upper half = hi
__device__ __forceinline__ uint32_t pk2(float lo, float hi) {
    uint32_t r;
    asm("cvt.rn.bf16x2.f32 %0, %1, %2;" : "=r"(r) : "f"(hi), "f"(lo));
    return r;
}

__device__ __forceinline__ void mma16816(float* c, uint32_t a0, uint32_t a1,
                                         uint32_t a2, uint32_t a3,
                                         uint32_t b0, uint32_t b1) {
    asm volatile(
        "mma.sync.aligned.m16n8k16.row.col.f32.bf16.bf16.f32 "
        "{%0,%1,%2,%3}, {%4,%5,%6,%7}, {%8,%9}, {%0,%1,%2,%3};"
        : "+f"(c[0]), "+f"(c[1]), "+f"(c[2]), "+f"(c[3])
        : "r"(a0), "r"(a1), "r"(a2), "r"(a3), "r"(b0), "r"(b1));
}

// ---------------------------------------------------------------------------
// Fused GEMM via mma.sync bf16 (3-way split for fp32 accuracy):
//   out = (LE+feats)@W1^T + (LE*feats)@W2^T + (b1+b2)
// Persistent, 1 CTA/SM, 256 threads (8 warps: 2x4 m/n grid).
// Block tile: 64 rows x 128 cols, K per phase = 128, 2 phases (a/W1, e/W2),
// 3 bf16-split products each.
// ---------------------------------------------------------------------------
#define APAD 136   // row length (elems) for A tiles -> bank-conflict-free frags
#define WPAD 136

#define OFF_AH  0
#define OFF_AL  (OFF_AH + 64 * APAD * 2)
#define OFF_EH  (OFF_AL + 64 * APAD * 2)
#define OFF_EL  (OFF_EH + 64 * APAD * 2)
#define OFF_W1H (OFF_EL + 64 * APAD * 2)
#define OFF_W1L (OFF_W1H + 128 * WPAD * 2)
#define OFF_W2H (OFF_W1L + 128 * WPAD * 2)
#define OFF_W2L (OFF_W2H + 128 * WPAD * 2)
#define OFF_BIAS (OFF_W2L + 128 * WPAD * 2)
#define SMEM_TOTAL_MM (OFF_BIAS + 128 * 4)

__global__ void __launch_bounds__(256, 1)
gemm_mm_kernel(const float* __restrict__ feats,
               const float* __restrict__ W1, const float* __restrict__ b1,
               const float* __restrict__ W2, const float* __restrict__ b2,
               float* __restrict__ out, int N, int nTiles) {
    extern __shared__ char smem[];

    int tid = threadIdx.x;
    int wid = tid >> 5;
    int lane = tid & 31;
    int wm = wid & 1;        // 0..1 : 32-row slice
    int wn = wid >> 1;       // 0..3 : 32-col slice
    int grp = lane >> 2;     // 0..7
    int quad = lane & 3;     // 0..3

    // ---- one-time: split W1/W2 into bf16 hi/lo in smem; bias ----
    for (int i = tid; i < FDIM * FDIM; i += 256) {
        int n = i >> 7;
        int k = i & 127;
        float w1 = W1[i];
        float w2 = W2[i];
        uint32_t h1 = pk2(w1, 0.f) & 0xFFFFu;       // bf16(w1) bits
        uint32_t h2 = pk2(w2, 0.f) & 0xFFFFu;
        float r1 = w1 - __uint_as_float(h1 << 16);
        float r2 = w2 - __uint_as_float(h2 << 16);
        uint32_t l1 = pk2(r1, 0.f) & 0xFFFFu;
        uint32_t l2 = pk2(r2, 0.f) & 0xFFFFu;
        size_t o = (size_t)(n * WPAD + k) * 2;
        *(uint16_t*)(smem + OFF_W1H + o) = (uint16_t)h1;
        *(uint16_t*)(smem + OFF_W1L + o) = (uint16_t)l1;
        *(uint16_t*)(smem + OFF_W2H + o) = (uint16_t)h2;
        *(uint16_t*)(smem + OFF_W2L + o) = (uint16_t)l2;
    }
    for (int i = tid; i < FDIM; i += 256)
        *(float*)(smem + OFF_BIAS + i * 4) = b1[i] + b2[i];
    __syncthreads();

    // Per-thread bias values for the 4 n-tiles (cols fixed per thread).
    float bv[4][2];
#pragma unroll
    for (int j = 0; j < 4; ++j) {
        int col = wn * 32 + j * 8 + quad * 2;
        bv[j][0] = *(float*)(smem + OFF_BIAS + col * 4);
        bv[j][1] = *(float*)(smem + OFF_BIAS + (col + 1) * 4);
    }

    for (int tile = blockIdx.x; tile < nTiles; tile += gridDim.x) {
        int row0 = tile << 6;

        // ---- convert 64x128 (LE,feats) -> ah/al/eh/el bf16 smem tiles ----
#pragma unroll
        for (int i = 0; i < 8; ++i) {
            int chunk = tid + i * 256;       // 0..2047
            int r = chunk >> 5;              // 0..63
            int k = (chunk & 31) << 2;       // 0..124
            int row = row0 + r;
            float4 le = make_float4(0.f, 0.f, 0.f, 0.f);
            float4 ft = le;
            if (row < N) {
                le = *(const float4*)&g_LE[(size_t)row * FDIM + k];
                ft = *(const float4*)&feats[(size_t)row * FDIM + k];
            }
            float a0 = le.x + ft.x, a1 = le.y + ft.y;
            float a2 = le.z + ft.z, a3 = le.w + ft.w;
            float e0 = le.x * ft.x, e1 = le.y * ft.y;
            float e2 = le.z * ft.z, e3 = le.w * ft.w;

            size_t o = (size_t)(r * APAD + k) * 2;

            uint32_t ah01 = pk2(a0, a1), ah23 = pk2(a2, a3);
            float ar0 = a0 - __uint_as_float(ah01 << 16);
            float ar1 = a1 - __uint_as_float(ah01 & 0xFFFF0000u);
            float ar2 = a2 - __uint_as_float(ah23 << 16);
            float ar3 = a3 - __uint_as_float(ah23 & 0xFFFF0000u);
            *(uint2*)(smem + OFF_AH + o) = make_uint2(ah01, ah23);
            *(uint2*)(smem + OFF_AL + o) = make_uint2(pk2(ar0, ar1), pk2(ar2, ar3));

            uint32_t eh01 = pk2(e0, e1), eh23 = pk2(e2, e3);
            float er0 = e0 - __uint_as_float(eh01 << 16);
            float er1 = e1 - __uint_as_float(eh01 & 0xFFFF0000u);
            float er2 = e2 - __uint_as_float(eh23 << 16);
            float er3 = e3 - __uint_as_float(eh23 & 0xFFFF0000u);
            *(uint2*)(smem + OFF_EH + o) = make_uint2(eh01, eh23);
            *(uint2*)(smem + OFF_EL + o) = make_uint2(pk2(er0, er1), pk2(er2, er3));
        }
        __syncthreads();

        // ---- MMA mainloop ----
        float acc[2][4][4];   // [m-tile][n-tile][frag]
#pragma unroll
        for (int mt = 0; mt < 2; ++mt)
#pragma unroll
            for (int nt = 0; nt < 4; ++nt)
#pragma unroll
                for (int f = 0; f < 4; ++f) acc[mt][nt][f] = 0.f;

        // 6 sub-gemms: phase a: (AH,W1H) (AL,W1H) (AH,W1L); phase e likewise.
        const int aoff[6] = {OFF_AH, OFF_AL, OFF_AH, OFF_EH, OFF_EL, OFF_EH};
        const int woff[6] = {OFF_W1H, OFF_W1H, OFF_W1L, OFF_W2H, OFF_W2H, OFF_W2L};

#pragma unroll
        for (int sg = 0; sg < 6; ++sg) {
            const char* sA = smem + aoff[sg];
            const char* sW = smem + woff[sg];
#pragma unroll
            for (int ks = 0; ks < 8; ++ks) {
                int kb = ks * 16 + quad * 2;
                // B fragments: 4 n-tiles x 2 regs
                uint32_t b[4][2];
#pragma unroll
                for (int nt = 0; nt < 4; ++nt) {
                    int n = wn * 32 + nt * 8 + grp;
                    b[nt][0] = *(const uint32_t*)(sW + (size_t)(n * WPAD + kb) * 2);
                    b[nt][1] = *(const uint32_t*)(sW + (size_t)(n * WPAD + kb + 8) * 2);
                }
#pragma unroll
                for (int mt = 0; mt < 2; ++mt) {
                    int rA = wm * 32 + mt * 16 + grp;
                    uint32_t a0 = *(const uint32_t*)(sA + (size_t)(rA * APAD + kb) * 2);
                    uint32_t a1 = *(const uint32_t*)(sA + (size_t)((rA + 8) * APAD + kb) * 2);
                    uint32_t a2 = *(const uint32_t*)(sA + (size_t)(rA * APAD + kb + 8) * 2);
                    uint32_t a3 = *(const uint32_t*)(sA + (size_t)((rA + 8) * APAD + kb + 8) * 2);
#pragma unroll
                    for (int nt = 0; nt < 4; ++nt)
                        mma16816(acc[mt][nt], a0, a1, a2, a3, b[nt][0], b[nt][1]);
                }
            }
        }

        // ---- epilogue: acc + bias -> out ----
#pragma unroll
        for (int mt = 0; mt < 2; ++mt) {
            int r_lo = row0 + wm * 32 + mt * 16 + grp;
            int r_hi = r_lo + 8;
#pragma unroll
            for (int nt = 0; nt < 4; ++nt) {
                int col = wn * 32 + nt * 8 + quad * 2;
                if (r_lo < N) {
                    float2 o;
                    o.x = acc[mt][nt][0] + bv[nt][0];
                    o.y = acc[mt][nt][1] + bv[nt][1];
                    *(float2*)&out[(size_t)r_lo * FDIM + col] = o;
                }
                if (r_hi < N) {
                    float2 o;
                    o.x = acc[mt][nt][2] + bv[nt][0];
                    o.y = acc[mt][nt][3] + bv[nt][1];
                    *(float2*)&out[(size_t)r_hi * FDIM + col] = o;
                }
            }
        }
        __syncthreads();
    }
}

// ---------------------------------------------------------------------------
extern "C" void kernel_launch(void* const* d_in, const int* in_sizes, int n_in,
                              void* d_out, int out_size) {
    const int*   src   = (const int*)d_in[0];
    const int*   dst   = (const int*)d_in[1];
    const float* val   = (const float*)d_in[2];
    const float* feats = (const float*)d_in[3];
    const float* W1    = (const float*)d_in[4];
    const float* b1    = (const float*)d_in[5];
    const float* W2    = (const float*)d_in[6];
    const float* b2    = (const float*)d_in[7];
    float* out = (float*)d_out;

    int E = in_sizes[0];
    int N = in_sizes[3] / FDIM;
    int nseg = (N + SEG - 1) / SEG;
    int nTiles = (N + 63) / 64;

    cudaFuncSetAttribute(gemm_mm_kernel,
                         cudaFuncAttributeMaxDynamicSharedMemorySize,
                         SMEM_TOTAL_MM);

    zero_cnt_kernel<<<(N + 255) / 256, 256>>>(N);
    hist_kernel<<<(E + 255) / 256, 256>>>(dst, E);
    scan1_kernel<<<nseg, 256>>>(N);
    scan2_kernel<<<1, MAXSEG>>>(nseg, N, E);
    scan3_kernel<<<nseg, 256>>>(N);
    permute_kernel<<<(E + 255) / 256, 256>>>(src, dst, val, E);
    gather_kernel<<<(N + 7) / 8, 256>>>(feats, N);

    int grid = nTiles < 148 ? nTiles : 148;
    gemm_mm_kernel<<<grid, 256, SMEM_TOTAL_MM>>>(feats, W1, b1, W2, b2, out,
                                                 N, nTiles);
}